// round 11
// baseline (speedup 1.0000x reference)
#include <cuda_runtime.h>
#include <cuda_bf16.h>
#include <math.h>

#define BATCH 8
#define SEQ   2048
#define EMB   1024
#define HD    128
#define MROWS (BATCH*SEQ)

// Projected q,k,v as bf16 hi/lo pairs (split once in proj epilogue)
__device__ __align__(16) __nv_bfloat16 g_qh[MROWS*HD];
__device__ __align__(16) __nv_bfloat16 g_ql[MROWS*HD];
__device__ __align__(16) __nv_bfloat16 g_kh[MROWS*HD];
__device__ __align__(16) __nv_bfloat16 g_kl[MROWS*HD];
__device__ __align__(16) __nv_bfloat16 g_vh[MROWS*HD];
__device__ __align__(16) __nv_bfloat16 g_vl[MROWS*HD];
// persistent-attention work counter (zeroed by proj block (0,0) each launch)
__device__ unsigned g_tile_ctr;

// ---------------------------------------------------------------------------
// helpers
// ---------------------------------------------------------------------------
__device__ __forceinline__ void split2(float x, float y, unsigned& hi, unsigned& lo) {
    asm("cvt.rn.bf16x2.f32 %0, %1, %2;" : "=r"(hi) : "f"(y), "f"(x));
    float rx = x - __uint_as_float(hi << 16);
    float ry = y - __uint_as_float(hi & 0xffff0000u);
    asm("cvt.rn.bf16x2.f32 %0, %1, %2;" : "=r"(lo) : "f"(ry), "f"(rx));
}
__device__ __forceinline__ void store_split4(char* hbase, char* lbase, int off2, float4 v) {
    unsigned h0, l0, h1, l1;
    split2(v.x, v.y, h0, l0);
    split2(v.z, v.w, h1, l1);
    *(uint2*)(hbase + (size_t)off2*2) = make_uint2(h0, h1);
    *(uint2*)(lbase + (size_t)off2*2) = make_uint2(l0, l1);
}
__device__ __forceinline__ void ldsm4(unsigned* r, unsigned addr) {
    asm volatile("ldmatrix.sync.aligned.m8n8.x4.shared.b16 {%0,%1,%2,%3}, [%4];"
        : "=r"(r[0]), "=r"(r[1]), "=r"(r[2]), "=r"(r[3]) : "r"(addr));
}
__device__ __forceinline__ void ldsm4t(unsigned* r, unsigned addr) {
    asm volatile("ldmatrix.sync.aligned.m8n8.x4.trans.shared.b16 {%0,%1,%2,%3}, [%4];"
        : "=r"(r[0]), "=r"(r[1]), "=r"(r[2]), "=r"(r[3]) : "r"(addr));
}
__device__ __forceinline__ void mma_bf16(float* d, const unsigned* a, unsigned b0, unsigned b1) {
    asm volatile("mma.sync.aligned.m16n8k16.row.col.f32.bf16.bf16.f32 "
        "{%0,%1,%2,%3}, {%4,%5,%6,%7}, {%8,%9}, {%0,%1,%2,%3};"
        : "+f"(d[0]), "+f"(d[1]), "+f"(d[2]), "+f"(d[3])
        : "r"(a[0]), "r"(a[1]), "r"(a[2]), "r"(a[3]), "r"(b0), "r"(b1));
}
__device__ __forceinline__ void cp16(unsigned dst, const void* src) {
    asm volatile("cp.async.ca.shared.global [%0], [%1], 16;" :: "r"(dst), "l"(src));
}

// ---------------------------------------------------------------------------
// Kernel 1: QKV projection (round-6 measured version).
// Block 128m x 128n, k-chunks of 64, 256 threads (8 warps, 4m x 2n),
// register-prefetch pipelined; epilogue writes bf16 hi/lo split.
// ---------------------------------------------------------------------------
#define PJ_XH 0
#define PJ_XL 18432
#define PJ_WH 36864
#define PJ_WL 54272
#define PJ_SMEM 71680

__global__ __launch_bounds__(256) void qkv_proj_bf16(
    const float* __restrict__ x,
    const float* __restrict__ Wk,
    const float* __restrict__ Wq,
    const float* __restrict__ Wv)
{
    extern __shared__ char smraw[];
    const unsigned sb = (unsigned)__cvta_generic_to_shared(smraw);

    if (blockIdx.x == 0 && blockIdx.y == 0 && threadIdx.x == 0)
        g_tile_ctr = 0;   // reset persistent-attn counter (stream-ordered before attn)

    const int t = threadIdx.x, lane = t & 31, w = t >> 5;
    const int g = lane >> 2, tg = lane & 3;
    const int wm = w >> 1, wn = w & 1;
    const int rowBase = blockIdx.x * 128;

    const float* W;
    __nv_bfloat16 *oh, *ol;
    if (blockIdx.y == 0)      { W = Wq; oh = g_qh; ol = g_ql; }
    else if (blockIdx.y == 1) { W = Wk; oh = g_kh; ol = g_kl; }
    else                      { W = Wv; oh = g_vh; ol = g_vl; }

    float acc[2][8][4];
    #pragma unroll
    for (int mf = 0; mf < 2; mf++)
        #pragma unroll
        for (int nb = 0; nb < 8; nb++)
            #pragma unroll
            for (int j = 0; j < 4; j++) acc[mf][nb][j] = 0.f;

    // prefetch registers
    float4 xr[8], wr[8];
    #pragma unroll
    for (int i = 0; i < 8; i++) {
        int idx = t + i*256;
        int r = idx >> 4, c4 = (idx & 15)*4;
        xr[i] = *(const float4*)(x + (size_t)(rowBase + r)*EMB + c4);
        int kk = idx >> 5, n4 = (idx & 31)*4;
        wr[i] = *(const float4*)(W + (size_t)kk*HD + n4);
    }

    for (int kc = 0; kc < 16; kc++) {
        // store prefetched chunk (split) into smem
        #pragma unroll
        for (int i = 0; i < 8; i++) {
            int idx = t + i*256;
            int r = idx >> 4, c4 = (idx & 15)*4;
            store_split4(smraw + PJ_XH, smraw + PJ_XL, r*72 + c4, xr[i]);
            int kk = idx >> 5, n4 = (idx & 31)*4;
            store_split4(smraw + PJ_WH, smraw + PJ_WL, kk*136 + n4, wr[i]);
        }
        __syncthreads();

        // issue next chunk's global loads (in flight during mma)
        if (kc < 15) {
            const int k0 = (kc + 1)*64;
            #pragma unroll
            for (int i = 0; i < 8; i++) {
                int idx = t + i*256;
                int r = idx >> 4, c4 = (idx & 15)*4;
                xr[i] = *(const float4*)(x + (size_t)(rowBase + r)*EMB + k0 + c4);
                int kk = idx >> 5, n4 = (idx & 31)*4;
                wr[i] = *(const float4*)(W + (size_t)(k0 + kk)*HD + n4);
            }
        }

        #pragma unroll
        for (int ks = 0; ks < 4; ks++) {
            unsigned ah[2][4], al[2][4];
            #pragma unroll
            for (int mf = 0; mf < 2; mf++) {
                unsigned aoff = ((wm*32 + mf*16 + (lane & 15))*72 + ks*16 + (lane >> 4)*8)*2;
                ldsm4(ah[mf], sb + PJ_XH + aoff);
                ldsm4(al[mf], sb + PJ_XL + aoff);
            }
            unsigned bh[4][4], bl[4][4];
            #pragma unroll
            for (int nb2 = 0; nb2 < 4; nb2++) {
                int krow = ks*16 + (lane & 7) + ((lane >> 3) & 1)*8;
                int ncol = wn*64 + nb2*16 + (lane >> 4)*8;
                unsigned boff = (krow*136 + ncol)*2;
                ldsm4t(bh[nb2], sb + PJ_WH + boff);
                ldsm4t(bl[nb2], sb + PJ_WL + boff);
            }
            #pragma unroll
            for (int mf = 0; mf < 2; mf++)
                #pragma unroll
                for (int nb = 0; nb < 8; nb++) {
                    const int nb2 = nb >> 1, h = (nb & 1)*2;
                    mma_bf16(acc[mf][nb], ah[mf], bh[nb2][h], bh[nb2][h+1]);
                    mma_bf16(acc[mf][nb], ah[mf], bl[nb2][h], bl[nb2][h+1]);
                    mma_bf16(acc[mf][nb], al[mf], bh[nb2][h], bh[nb2][h+1]);
                }
        }
        __syncthreads();
    }

    // epilogue: split fp32 acc -> bf16 hi/lo global
    #pragma unroll
    for (int mf = 0; mf < 2; mf++) {
        size_t rA = (size_t)(rowBase + wm*32 + mf*16 + g);
        #pragma unroll
        for (int nb = 0; nb < 8; nb++) {
            int col = wn*64 + nb*8 + tg*2;
            unsigned hi, lo;
            split2(acc[mf][nb][0], acc[mf][nb][1], hi, lo);
            *(unsigned*)(oh + rA*HD + col) = hi;
            *(unsigned*)(ol + rA*HD + col) = lo;
            split2(acc[mf][nb][2], acc[mf][nb][3], hi, lo);
            *(unsigned*)(oh + (rA + 8)*HD + col) = hi;
            *(unsigned*)(ol + (rA + 8)*HD + col) = lo;
        }
    }
}

// ---------------------------------------------------------------------------
// Kernel 2: persistent causal flash attention, bf16 3-product mma, 2 CTAs/SM.
// Single-stage K/V (split K/V commit groups), Q-hi hoisted to regs (staged via
// the K/V buffer), Q-lo in smem. 256 threads (8 warps, 4m x 2n), grid 296.
// smem (bytes):
//   Qlo @0 (64 x 272B rows = 17408)
//   STG @17408 (single stage): Kh +0, Kl +17408, Vh +34816, Vl +52224  (69632)
//   PH @87040 (9216)  PL @96256 (9216)
//   Mx @105472 (512)  Sx @105984 (512)  m_s @106496 (256)  l_s @106752 (256)
//   tile-id @107008   total 107024  -> 2 CTAs/SM (214048 <= 228KB/SM)
// ---------------------------------------------------------------------------
#define AT_QL 0
#define AT_STG 17408
#define AT_PH 87040
#define AT_PL 96256
#define AT_MX 105472
#define AT_SX 105984
#define AT_MS 106496
#define AT_LS 106752
#define AT_TID 107008
#define AT_SMEM 107024

#define N_TILES 256
#define ATT_GRID 296

__global__ __launch_bounds__(256, 2) void attn_bf16_kernel(float* __restrict__ out)
{
    extern __shared__ char smraw[];
    const unsigned sb = (unsigned)__cvta_generic_to_shared(smraw);
    float* Mx  = (float*)(smraw + AT_MX);
    float* Sx  = (float*)(smraw + AT_SX);
    float* m_s = (float*)(smraw + AT_MS);
    float* l_s = (float*)(smraw + AT_LS);
    unsigned* tid_s = (unsigned*)(smraw + AT_TID);

    const int t = threadIdx.x, lane = t & 31, w = t >> 5;
    const int g = lane >> 2, tg = lane & 3;
    const int wm = w >> 1, wn = w & 1;
    const int M0 = wm * 16;

    const float scale = 0.08838834764831845f;  // 128^-0.5

    for (;;) {
        // grab next tile (heavy tiles first: n ascending -> qt descending)
        if (t == 0) *tid_s = atomicAdd(&g_tile_ctr, 1u);
        __syncthreads();
        const unsigned n = *tid_s;
        if (n >= N_TILES) return;
        const int b  = (int)(n & 7);
        const int qt = 31 - (int)(n >> 3);
        const int qbase = qt * 64;

        const size_t boff = (size_t)b*SEQ*HD;
        const __nv_bfloat16 *qh = g_qh + boff, *ql = g_ql + boff;
        const __nv_bfloat16 *kh = g_kh + boff, *kl = g_kl + boff;
        const __nv_bfloat16 *vh = g_vh + boff, *vl = g_vl + boff;

        // stage Q: hi -> STG (temporarily), lo -> permanent Qlo region
        #pragma unroll
        for (int i = 0; i < 4; i++) {
            int idx = t + i*256;
            int r = idx >> 4, c8 = idx & 15;
            size_t e = (size_t)(qbase + r)*HD + c8*8;
            cp16(sb + AT_STG + r*272 + c8*16, qh + e);
            cp16(sb + AT_QL  + r*272 + c8*16, ql + e);
        }
        asm volatile("cp.async.commit_group;");
        asm volatile("cp.async.wait_group 0;");
        __syncthreads();

        // hoist Q-hi fragments (loop-invariant) into registers
        unsigned qfh[8][4];
        #pragma unroll
        for (int ks = 0; ks < 8; ks++) {
            unsigned aoff = ((M0 + (lane & 15))*136 + ks*16 + (lane >> 4)*8)*2;
            ldsm4(qfh[ks], sb + AT_STG + aoff);
        }
        if (t < 64) { m_s[t] = -1e30f; l_s[t] = 0.f; }

        float o[8][4];
        #pragma unroll
        for (int f = 0; f < 8; f++)
            #pragma unroll
            for (int j = 0; j < 4; j++) o[f][j] = 0.f;

        __syncthreads();   // Q-hi ldsm done before K staging overwrites STG

        for (int kt = 0; kt <= qt; kt++) {
            const int kbase = kt * 64;
            const unsigned stK = sb + AT_STG;
            const unsigned stV = stK + 34816;

            if (kt > 0) __syncthreads();   // prior iter done reading STG
            // stage K (own commit group)
            #pragma unroll
            for (int i = 0; i < 4; i++) {
                int idx = t + i*256;
                int r = idx >> 4, c8 = idx & 15;
                size_t e = (size_t)(kbase + r)*HD + c8*8;
                unsigned d = stK + r*272 + c8*16;
                cp16(d,         kh + e);
                cp16(d + 17408, kl + e);
            }
            asm volatile("cp.async.commit_group;");
            // stage V (second group; waited only after softmax)
            #pragma unroll
            for (int i = 0; i < 4; i++) {
                int idx = t + i*256;
                int r = idx >> 4, c8 = idx & 15;
                size_t e = (size_t)(kbase + r)*HD + c8*8;
                unsigned d = stV + r*272 + c8*16;
                cp16(d,         vh + e);
                cp16(d + 17408, vl + e);
            }
            asm volatile("cp.async.commit_group;");
            asm volatile("cp.async.wait_group 1;");   // K ready (V may be in flight)
            __syncthreads();

            // ---- S = Q K^T : warp m16 x n32 ----
            float s[4][4];
            #pragma unroll
            for (int f = 0; f < 4; f++)
                #pragma unroll
                for (int j = 0; j < 4; j++) s[f][j] = 0.f;

            #pragma unroll
            for (int ks = 0; ks < 8; ks++) {
                unsigned a_l[4];
                {
                    unsigned aoff = ((M0 + (lane & 15))*136 + ks*16 + (lane >> 4)*8)*2;
                    ldsm4(a_l, sb + AT_QL + aoff);
                }
                unsigned bh[2][4], bl[2][4];
                #pragma unroll
                for (int nb2 = 0; nb2 < 2; nb2++) {
                    int nrow = wn*32 + nb2*16 + (lane & 7) + (lane >> 4)*8;
                    int koff = ks*16 + ((lane >> 3) & 1)*8;
                    unsigned bo = (nrow*136 + koff)*2;
                    ldsm4(bh[nb2], stK + bo);
                    ldsm4(bl[nb2], stK + 17408 + bo);
                }
                #pragma unroll
                for (int f = 0; f < 4; f++) {
                    const int nb2 = f >> 1, h = (f & 1)*2;
                    mma_bf16(s[f], qfh[ks], bh[nb2][h], bh[nb2][h+1]);
                    mma_bf16(s[f], qfh[ks], bl[nb2][h], bl[nb2][h+1]);
                    mma_bf16(s[f], a_l,     bh[nb2][h], bh[nb2][h+1]);
                }
            }

            // scale + causal mask
            const int rowA = qbase + M0 + g;
            const int rowB = rowA + 8;
            const bool diag = (kt == qt);
            #pragma unroll
            for (int f = 0; f < 4; f++) {
                int c = kbase + wn*32 + f*8 + tg*2;
                s[f][0] *= scale; s[f][1] *= scale; s[f][2] *= scale; s[f][3] *= scale;
                if (diag) {
                    if (c     > rowA) s[f][0] = -1e30f;
                    if (c + 1 > rowA) s[f][1] = -1e30f;
                    if (c     > rowB) s[f][2] = -1e30f;
                    if (c + 1 > rowB) s[f][3] = -1e30f;
                }
            }

            // warp-local row max, stash
            float mxA = fmaxf(fmaxf(s[0][0], s[0][1]), fmaxf(s[1][0], s[1][1]));
            mxA = fmaxf(mxA, fmaxf(fmaxf(s[2][0], s[2][1]), fmaxf(s[3][0], s[3][1])));
            float mxB = fmaxf(fmaxf(s[0][2], s[0][3]), fmaxf(s[1][2], s[1][3]));
            mxB = fmaxf(mxB, fmaxf(fmaxf(s[2][2], s[2][3]), fmaxf(s[3][2], s[3][3])));
            mxA = fmaxf(mxA, __shfl_xor_sync(0xffffffffu, mxA, 1));
            mxA = fmaxf(mxA, __shfl_xor_sync(0xffffffffu, mxA, 2));
            mxB = fmaxf(mxB, __shfl_xor_sync(0xffffffffu, mxB, 1));
            mxB = fmaxf(mxB, __shfl_xor_sync(0xffffffffu, mxB, 2));
            const float moldA = m_s[M0 + g];
            const float moldB = m_s[M0 + g + 8];
            if (tg == 0) {
                Mx[wn*64 + M0 + g]     = mxA;
                Mx[wn*64 + M0 + g + 8] = mxB;
            }
            __syncthreads();

            const float mA = fmaxf(moldA, fmaxf(Mx[M0 + g],     Mx[64 + M0 + g]));
            const float mB = fmaxf(moldB, fmaxf(Mx[M0 + g + 8], Mx[64 + M0 + g + 8]));
            const float alphaA = __expf(moldA - mA);
            const float alphaB = __expf(moldB - mB);
            if (wn == 0 && tg == 0) {
                m_s[M0 + g]     = mA;
                m_s[M0 + g + 8] = mB;
            }
            float sumA = 0.f, sumB = 0.f;
            #pragma unroll
            for (int f = 0; f < 4; f++) {
                float p0 = __expf(s[f][0] - mA);
                float p1 = __expf(s[f][1] - mA);
                float p2 = __expf(s[f][2] - mB);
                float p3 = __expf(s[f][3] - mB);
                sumA += p0 + p1; sumB += p2 + p3;
                int col = wn*32 + f*8 + tg*2;
                unsigned hi, lo;
                split2(p0, p1, hi, lo);
                *(unsigned*)(smraw + AT_PH + ((M0 + g)*72 + col)*2) = hi;
                *(unsigned*)(smraw + AT_PL + ((M0 + g)*72 + col)*2) = lo;
                split2(p2, p3, hi, lo);
                *(unsigned*)(smraw + AT_PH + ((M0 + g + 8)*72 + col)*2) = hi;
                *(unsigned*)(smraw + AT_PL + ((M0 + g + 8)*72 + col)*2) = lo;
            }
            sumA += __shfl_xor_sync(0xffffffffu, sumA, 1);
            sumA += __shfl_xor_sync(0xffffffffu, sumA, 2);
            sumB += __shfl_xor_sync(0xffffffffu, sumB, 1);
            sumB += __shfl_xor_sync(0xffffffffu, sumB, 2);
            if (tg == 0) {
                Sx[wn*64 + M0 + g]     = sumA;
                Sx[wn*64 + M0 + g + 8] = sumB;
            }
            asm volatile("cp.async.wait_group 0;");   // V arrived (hidden behind QK+softmax)
            __syncthreads();

            if (wn == 0 && tg == 0) {
                int r = M0 + g;
                l_s[r] = l_s[r]*alphaA + Sx[r] + Sx[64 + r];
                r += 8;
                l_s[r] = l_s[r]*alphaB + Sx[r] + Sx[64 + r];
            }

            // rescale O, then O += P V  (warp: m16 x d64)
            #pragma unroll
            for (int f = 0; f < 8; f++) {
                o[f][0] *= alphaA; o[f][1] *= alphaA;
                o[f][2] *= alphaB; o[f][3] *= alphaB;
            }
            #pragma unroll
            for (int ks2 = 0; ks2 < 4; ks2++) {
                unsigned a_h[4], a_l[4];
                {
                    unsigned aoff = ((M0 + (lane & 15))*72 + ks2*16 + (lane >> 4)*8)*2;
                    ldsm4(a_h, sb + AT_PH + aoff);
                    ldsm4(a_l, sb + AT_PL + aoff);
                }
                unsigned bh[2][4], bl[2][4];
                #pragma unroll
                for (int db2 = 0; db2 < 2; db2++) {
                    int srow = ks2*16 + (lane & 7) + ((lane >> 3) & 1)*8;
                    int dcol = wn*64 + db2*32 + (lane >> 4)*8;
                    unsigned bo = (srow*136 + dcol)*2;
                    ldsm4t(bh[db2], stV + bo);
                    ldsm4t(bl[db2], stV + 17408 + bo);
                }
                unsigned bh2[2][4], bl2[2][4];
                #pragma unroll
                for (int db2 = 0; db2 < 2; db2++) {
                    int srow = ks2*16 + (lane & 7) + ((lane >> 3) & 1)*8;
                    int dcol = wn*64 + db2*32 + 16 + (lane >> 4)*8;
                    unsigned bo = (srow*136 + dcol)*2;
                    ldsm4t(bh2[db2], stV + bo);
                    ldsm4t(bl2[db2], stV + 17408 + bo);
                }
                #pragma unroll
                for (int f = 0; f < 8; f++) {
                    const int db2 = f >> 2, sub = f & 3;
                    const unsigned* BH = (sub < 2) ? bh[db2] : bh2[db2];
                    const unsigned* BL = (sub < 2) ? bl[db2] : bl2[db2];
                    const int h = (sub & 1)*2;
                    mma_bf16(o[f], a_h, BH[h], BH[h+1]);
                    mma_bf16(o[f], a_h, BL[h], BL[h+1]);
                    mma_bf16(o[f], a_l, BH[h], BH[h+1]);
                }
            }
        }

        // epilogue
        __syncthreads();
        {
            const float invA = 1.f / l_s[M0 + g];
            const float invB = 1.f / l_s[M0 + g + 8];
            float* Ob = out + ((size_t)b*SEQ + qbase)*HD;
            size_t rA = (size_t)(M0 + g);
            #pragma unroll
            for (int f = 0; f < 8; f++) {
                const int db2 = f >> 2, sub = f & 3;
                int col = wn*64 + db2*32 + (sub >> 1)*16 + (sub & 1)*8 + tg*2;
                *(float2*)(Ob + rA*HD + col)       = make_float2(o[f][0]*invA, o[f][1]*invA);
                *(float2*)(Ob + (rA + 8)*HD + col) = make_float2(o[f][2]*invB, o[f][3]*invB);
            }
        }
        __syncthreads();   // epilogue reads done before next tile reuses smem
    }
}

// ---------------------------------------------------------------------------
extern "C" void kernel_launch(void* const* d_in, const int* in_sizes, int n_in,
                              void* d_out, int out_size)
{
    const float* x  = (const float*)d_in[0];
    const float* Wk = (const float*)d_in[1];
    const float* Wq = (const float*)d_in[2];
    const float* Wv = (const float*)d_in[3];
    float* out = (float*)d_out;

    cudaFuncSetAttribute(qkv_proj_bf16,
                         cudaFuncAttributeMaxDynamicSharedMemorySize, PJ_SMEM);
    cudaFuncSetAttribute(attn_bf16_kernel,
                         cudaFuncAttributeMaxDynamicSharedMemorySize, AT_SMEM);

    dim3 g1(MROWS/128, 3);
    qkv_proj_bf16<<<g1, 256, PJ_SMEM>>>(x, Wk, Wq, Wv);

    attn_bf16_kernel<<<ATT_GRID, 256, AT_SMEM>>>(out);
}

// round 13
// speedup vs baseline: 1.8012x; 1.8012x over previous
#include <cuda_runtime.h>
#include <cuda_fp16.h>
#include <math.h>

#define BATCH 8
#define SEQ   2048
#define EMB   1024
#define HD    128
#define MROWS (BATCH*SEQ)

// Projected q (hi/lo fp16), k (single fp16), v (hi/lo fp16)
__device__ __align__(16) __half g_qh[MROWS*HD];
__device__ __align__(16) __half g_ql[MROWS*HD];
__device__ __align__(16) __half g_kh[MROWS*HD];
__device__ __align__(16) __half g_vh[MROWS*HD];
__device__ __align__(16) __half g_vl[MROWS*HD];

// ---------------------------------------------------------------------------
// helpers
// ---------------------------------------------------------------------------
__device__ __forceinline__ unsigned packh2(float x, float y) {
    __half2 h = __floats2half2_rn(x, y);   // x in low half
    return *reinterpret_cast<unsigned*>(&h);
}
__device__ __forceinline__ void splith2(float x, float y, unsigned& hi, unsigned& lo) {
    hi = packh2(x, y);
    __half2 h = *reinterpret_cast<__half2*>(&hi);
    float2 f = __half22float2(h);
    lo = packh2(x - f.x, y - f.y);
}
__device__ __forceinline__ void ldsm4(unsigned* r, unsigned addr) {
    asm volatile("ldmatrix.sync.aligned.m8n8.x4.shared.b16 {%0,%1,%2,%3}, [%4];"
        : "=r"(r[0]), "=r"(r[1]), "=r"(r[2]), "=r"(r[3]) : "r"(addr));
}
__device__ __forceinline__ void ldsm4t(unsigned* r, unsigned addr) {
    asm volatile("ldmatrix.sync.aligned.m8n8.x4.trans.shared.b16 {%0,%1,%2,%3}, [%4];"
        : "=r"(r[0]), "=r"(r[1]), "=r"(r[2]), "=r"(r[3]) : "r"(addr));
}
__device__ __forceinline__ void mma_f16(float* d, const unsigned* a, unsigned b0, unsigned b1) {
    asm volatile("mma.sync.aligned.m16n8k16.row.col.f32.f16.f16.f32 "
        "{%0,%1,%2,%3}, {%4,%5,%6,%7}, {%8,%9}, {%0,%1,%2,%3};"
        : "+f"(d[0]), "+f"(d[1]), "+f"(d[2]), "+f"(d[3])
        : "r"(a[0]), "r"(a[1]), "r"(a[2]), "r"(a[3]), "r"(b0), "r"(b1));
}
__device__ __forceinline__ void cp16(unsigned dst, const void* src) {
    asm volatile("cp.async.ca.shared.global [%0], [%1], 16;" :: "r"(dst), "l"(src));
}

// ---------------------------------------------------------------------------
// Kernel 1: QKV projection, fp16 2-product (x single, W hi/lo),
// register-prefetch pipelined (round-6 structure).
// Block 128m x 128n, k-chunks of 64, 256 threads (8 warps, 4m x 2n).
// smem: XS[128][72] @0 (18432), WH[64][136] @18432, WL @35840  total 53248
// ---------------------------------------------------------------------------
#define PJ_XS 0
#define PJ_WH 18432
#define PJ_WL 35840
#define PJ_SMEM 53248

__global__ __launch_bounds__(256) void qkv_proj_f16(
    const float* __restrict__ x,
    const float* __restrict__ Wk,
    const float* __restrict__ Wq,
    const float* __restrict__ Wv)
{
    extern __shared__ char smraw[];
    const unsigned sb = (unsigned)__cvta_generic_to_shared(smraw);

    const int t = threadIdx.x, lane = t & 31, w = t >> 5;
    const int g = lane >> 2, tg = lane & 3;
    const int wm = w >> 1, wn = w & 1;
    const int rowBase = blockIdx.x * 128;

    const float* W;
    __half *oh, *ol;
    bool wantLo;
    if (blockIdx.y == 0)      { W = Wq; oh = g_qh; ol = g_ql; wantLo = true;  }
    else if (blockIdx.y == 1) { W = Wk; oh = g_kh; ol = 0;    wantLo = false; }
    else                      { W = Wv; oh = g_vh; ol = g_vl; wantLo = true;  }

    float acc[2][8][4];
    #pragma unroll
    for (int mf = 0; mf < 2; mf++)
        #pragma unroll
        for (int nb = 0; nb < 8; nb++)
            #pragma unroll
            for (int j = 0; j < 4; j++) acc[mf][nb][j] = 0.f;

    // prefetch registers
    float4 xr[8], wr[8];
    #pragma unroll
    for (int i = 0; i < 8; i++) {
        int idx = t + i*256;
        int r = idx >> 4, c4 = (idx & 15)*4;
        xr[i] = *(const float4*)(x + (size_t)(rowBase + r)*EMB + c4);
        int kk = idx >> 5, n4 = (idx & 31)*4;
        wr[i] = *(const float4*)(W + (size_t)kk*HD + n4);
    }

    for (int kc = 0; kc < 16; kc++) {
        // store prefetched chunk into smem (x single fp16, W split)
        #pragma unroll
        for (int i = 0; i < 8; i++) {
            int idx = t + i*256;
            int r = idx >> 4, c4 = (idx & 15)*4;
            *(uint2*)(smraw + PJ_XS + (r*72 + c4)*2) =
                make_uint2(packh2(xr[i].x, xr[i].y), packh2(xr[i].z, xr[i].w));
            int kk = idx >> 5, n4 = (idx & 31)*4;
            unsigned h0, l0, h1, l1;
            splith2(wr[i].x, wr[i].y, h0, l0);
            splith2(wr[i].z, wr[i].w, h1, l1);
            *(uint2*)(smraw + PJ_WH + (kk*136 + n4)*2) = make_uint2(h0, h1);
            *(uint2*)(smraw + PJ_WL + (kk*136 + n4)*2) = make_uint2(l0, l1);
        }
        __syncthreads();

        // issue next chunk's global loads (in flight during mma)
        if (kc < 15) {
            const int k0 = (kc + 1)*64;
            #pragma unroll
            for (int i = 0; i < 8; i++) {
                int idx = t + i*256;
                int r = idx >> 4, c4 = (idx & 15)*4;
                xr[i] = *(const float4*)(x + (size_t)(rowBase + r)*EMB + k0 + c4);
                int kk = idx >> 5, n4 = (idx & 31)*4;
                wr[i] = *(const float4*)(W + (size_t)(k0 + kk)*HD + n4);
            }
        }

        #pragma unroll
        for (int ks = 0; ks < 4; ks++) {
            unsigned ah[2][4];
            #pragma unroll
            for (int mf = 0; mf < 2; mf++) {
                unsigned aoff = ((wm*32 + mf*16 + (lane & 15))*72 + ks*16 + (lane >> 4)*8)*2;
                ldsm4(ah[mf], sb + PJ_XS + aoff);
            }
            unsigned bh[4][4], bl[4][4];
            #pragma unroll
            for (int nb2 = 0; nb2 < 4; nb2++) {
                int krow = ks*16 + (lane & 7) + ((lane >> 3) & 1)*8;
                int ncol = wn*64 + nb2*16 + (lane >> 4)*8;
                unsigned boff = (krow*136 + ncol)*2;
                ldsm4t(bh[nb2], sb + PJ_WH + boff);
                ldsm4t(bl[nb2], sb + PJ_WL + boff);
            }
            #pragma unroll
            for (int mf = 0; mf < 2; mf++)
                #pragma unroll
                for (int nb = 0; nb < 8; nb++) {
                    const int nb2 = nb >> 1, h = (nb & 1)*2;
                    mma_f16(acc[mf][nb], ah[mf], bh[nb2][h], bh[nb2][h+1]);
                    mma_f16(acc[mf][nb], ah[mf], bl[nb2][h], bl[nb2][h+1]);
                }
        }
        __syncthreads();
    }

    // epilogue: q/v -> fp16 hi/lo split; k -> single fp16
    #pragma unroll
    for (int mf = 0; mf < 2; mf++) {
        size_t rA = (size_t)(rowBase + wm*32 + mf*16 + g);
        #pragma unroll
        for (int nb = 0; nb < 8; nb++) {
            int col = wn*64 + nb*8 + tg*2;
            unsigned hi, lo;
            splith2(acc[mf][nb][0], acc[mf][nb][1], hi, lo);
            *(unsigned*)(oh + rA*HD + col) = hi;
            if (wantLo) *(unsigned*)(ol + rA*HD + col) = lo;
            splith2(acc[mf][nb][2], acc[mf][nb][3], hi, lo);
            *(unsigned*)(oh + (rA + 8)*HD + col) = hi;
            if (wantLo) *(unsigned*)(ol + (rA + 8)*HD + col) = lo;
        }
    }
}

// ---------------------------------------------------------------------------
// Kernel 2: causal flash attention, fp16 2-product, cp.async double-buffered,
// Q (hi+lo) fragments hoisted. 256 threads, 8 warps (4m x 2n), grid 256.
// QK: S = (Qh+Ql) * Kh.  PV: O = Ph * (Vh+Vl).
// smem (bytes):
//   Qh @0  Ql @17408                 (64 x 272B rows)
//   stage s in {0,1} @34816 + s*52224 : Kh +0, Vh +17408, Vl +34816
//   PH @139264 (9216)
//   Mx @148480 (512)  Sx @148992 (512)  m_s @149504  l_s @149760  total 150016
// ---------------------------------------------------------------------------
#define AT_QH 0
#define AT_QL 17408
#define AT_STG 34816
#define AT_PH 139264
#define AT_MX 148480
#define AT_SX 148992
#define AT_MS 149504
#define AT_LS 149760
#define AT_SMEM 150016

__device__ __forceinline__ void stage_kv(unsigned sb, int stage, int t,
                                         const __half* kh0,
                                         const __half* vh0, const __half* vl0,
                                         int kbase)
{
    const unsigned base = sb + AT_STG + stage*52224;
    #pragma unroll
    for (int i = 0; i < 4; i++) {
        int idx = t + i*256;
        int r = idx >> 4, c8 = idx & 15;
        size_t e = (size_t)(kbase + r)*HD + c8*8;
        unsigned d = base + r*272 + c8*16;
        cp16(d,         kh0 + e);
        cp16(d + 17408, vh0 + e);
        cp16(d + 34816, vl0 + e);
    }
}

__global__ __launch_bounds__(256) void attn_f16_kernel(float* __restrict__ out)
{
    extern __shared__ char smraw[];
    const unsigned sb = (unsigned)__cvta_generic_to_shared(smraw);
    float* Mx  = (float*)(smraw + AT_MX);
    float* Sx  = (float*)(smraw + AT_SX);
    float* m_s = (float*)(smraw + AT_MS);
    float* l_s = (float*)(smraw + AT_LS);

    const int blk = blockIdx.x;
    const int b   = blk & 7;
    const int qt  = (SEQ/64 - 1) - (blk >> 3);   // heavy tiles first
    const int qbase = qt * 64;

    const int t = threadIdx.x, lane = t & 31, w = t >> 5;
    const int g = lane >> 2, tg = lane & 3;
    const int wm = w >> 1, wn = w & 1;
    const int M0 = wm * 16;

    const size_t boff = (size_t)b*SEQ*HD;
    const __half *qh = g_qh + boff, *ql = g_ql + boff;
    const __half *kh = g_kh + boff;
    const __half *vh = g_vh + boff, *vl = g_vl + boff;

    // stage Q (once) + first K/V stage, one commit group; drain so Q can be hoisted
    #pragma unroll
    for (int i = 0; i < 4; i++) {
        int idx = t + i*256;
        int r = idx >> 4, c8 = idx & 15;
        size_t e = (size_t)(qbase + r)*HD + c8*8;
        cp16(sb + AT_QH + r*272 + c8*16, qh + e);
        cp16(sb + AT_QL + r*272 + c8*16, ql + e);
    }
    stage_kv(sb, 0, t, kh, vh, vl, 0);
    asm volatile("cp.async.commit_group;");

    if (t < 64) { m_s[t] = -1e30f; l_s[t] = 0.f; }

    asm volatile("cp.async.wait_group 0;");
    __syncthreads();

    // hoist Q fragments (loop-invariant) into registers
    unsigned qfh[8][4], qfl[8][4];
    #pragma unroll
    for (int ks = 0; ks < 8; ks++) {
        unsigned aoff = ((M0 + (lane & 15))*136 + ks*16 + (lane >> 4)*8)*2;
        ldsm4(qfh[ks], sb + AT_QH + aoff);
        ldsm4(qfl[ks], sb + AT_QL + aoff);
    }

    float o[8][4];
    #pragma unroll
    for (int f = 0; f < 8; f++)
        #pragma unroll
        for (int j = 0; j < 4; j++) o[f][j] = 0.f;

    const float scale = 0.08838834764831845f;  // 128^-0.5

    for (int kt = 0; kt <= qt; kt++) {
        const int kbase = kt * 64;
        const int cur = kt & 1;
        const unsigned stK  = sb + AT_STG + cur*52224;
        const unsigned stVh = stK + 17408;
        const unsigned stVl = stK + 34816;

        __syncthreads();   // all warps done reading the buffer about to be overwritten
        if (kt < qt) {
            stage_kv(sb, cur ^ 1, t, kh, vh, vl, kbase + 64);
            asm volatile("cp.async.commit_group;");
            asm volatile("cp.async.wait_group 1;");
        } else {
            asm volatile("cp.async.wait_group 0;");
        }
        __syncthreads();   // current buffer visible

        // ---- S = (Qh+Ql) Kh^T : warp m16 x n32 ----
        float s[4][4];
        #pragma unroll
        for (int f = 0; f < 4; f++)
            #pragma unroll
            for (int j = 0; j < 4; j++) s[f][j] = 0.f;

        #pragma unroll
        for (int ks = 0; ks < 8; ks++) {
            unsigned bh[2][4];
            #pragma unroll
            for (int nb2 = 0; nb2 < 2; nb2++) {
                int nrow = wn*32 + nb2*16 + (lane & 7) + (lane >> 4)*8;
                int koff = ks*16 + ((lane >> 3) & 1)*8;
                unsigned bo = (nrow*136 + koff)*2;
                ldsm4(bh[nb2], stK + bo);
            }
            #pragma unroll
            for (int f = 0; f < 4; f++) {
                const int nb2 = f >> 1, h = (f & 1)*2;
                mma_f16(s[f], qfh[ks], bh[nb2][h], bh[nb2][h+1]);
                mma_f16(s[f], qfl[ks], bh[nb2][h], bh[nb2][h+1]);
            }
        }

        // scale + causal mask
        const int rowA = qbase + M0 + g;
        const int rowB = rowA + 8;
        const bool diag = (kt == qt);
        #pragma unroll
        for (int f = 0; f < 4; f++) {
            int c = kbase + wn*32 + f*8 + tg*2;
            s[f][0] *= scale; s[f][1] *= scale; s[f][2] *= scale; s[f][3] *= scale;
            if (diag) {
                if (c     > rowA) s[f][0] = -1e30f;
                if (c + 1 > rowA) s[f][1] = -1e30f;
                if (c     > rowB) s[f][2] = -1e30f;
                if (c + 1 > rowB) s[f][3] = -1e30f;
            }
        }

        // warp-local row max, stash
        float mxA = fmaxf(fmaxf(s[0][0], s[0][1]), fmaxf(s[1][0], s[1][1]));
        mxA = fmaxf(mxA, fmaxf(fmaxf(s[2][0], s[2][1]), fmaxf(s[3][0], s[3][1])));
        float mxB = fmaxf(fmaxf(s[0][2], s[0][3]), fmaxf(s[1][2], s[1][3]));
        mxB = fmaxf(mxB, fmaxf(fmaxf(s[2][2], s[2][3]), fmaxf(s[3][2], s[3][3])));
        mxA = fmaxf(mxA, __shfl_xor_sync(0xffffffffu, mxA, 1));
        mxA = fmaxf(mxA, __shfl_xor_sync(0xffffffffu, mxA, 2));
        mxB = fmaxf(mxB, __shfl_xor_sync(0xffffffffu, mxB, 1));
        mxB = fmaxf(mxB, __shfl_xor_sync(0xffffffffu, mxB, 2));
        const float moldA = m_s[M0 + g];
        const float moldB = m_s[M0 + g + 8];
        if (tg == 0) {
            Mx[wn*64 + M0 + g]     = mxA;
            Mx[wn*64 + M0 + g + 8] = mxB;
        }
        __syncthreads();

        const float mA = fmaxf(moldA, fmaxf(Mx[M0 + g],     Mx[64 + M0 + g]));
        const float mB = fmaxf(moldB, fmaxf(Mx[M0 + g + 8], Mx[64 + M0 + g + 8]));
        const float alphaA = __expf(moldA - mA);
        const float alphaB = __expf(moldB - mB);
        if (wn == 0 && tg == 0) {
            m_s[M0 + g]     = mA;
            m_s[M0 + g + 8] = mB;
        }
        float sumA = 0.f, sumB = 0.f;
        #pragma unroll
        for (int f = 0; f < 4; f++) {
            float p0 = __expf(s[f][0] - mA);
            float p1 = __expf(s[f][1] - mA);
            float p2 = __expf(s[f][2] - mB);
            float p3 = __expf(s[f][3] - mB);
            sumA += p0 + p1; sumB += p2 + p3;
            int col = wn*32 + f*8 + tg*2;
            *(unsigned*)(smraw + AT_PH + ((M0 + g)*72 + col)*2)     = packh2(p0, p1);
            *(unsigned*)(smraw + AT_PH + ((M0 + g + 8)*72 + col)*2) = packh2(p2, p3);
        }
        sumA += __shfl_xor_sync(0xffffffffu, sumA, 1);
        sumA += __shfl_xor_sync(0xffffffffu, sumA, 2);
        sumB += __shfl_xor_sync(0xffffffffu, sumB, 1);
        sumB += __shfl_xor_sync(0xffffffffu, sumB, 2);
        if (tg == 0) {
            Sx[wn*64 + M0 + g]     = sumA;
            Sx[wn*64 + M0 + g + 8] = sumB;
        }
        __syncthreads();

        if (wn == 0 && tg == 0) {
            int r = M0 + g;
            l_s[r] = l_s[r]*alphaA + Sx[r] + Sx[64 + r];
            r += 8;
            l_s[r] = l_s[r]*alphaB + Sx[r] + Sx[64 + r];
        }

        // rescale O, then O += P (Vh+Vl)  (warp: m16 x d64)
        #pragma unroll
        for (int f = 0; f < 8; f++) {
            o[f][0] *= alphaA; o[f][1] *= alphaA;
            o[f][2] *= alphaB; o[f][3] *= alphaB;
        }
        #pragma unroll
        for (int ks2 = 0; ks2 < 4; ks2++) {
            unsigned a_h[4];
            {
                unsigned aoff = ((M0 + (lane & 15))*72 + ks2*16 + (lane >> 4)*8)*2;
                ldsm4(a_h, sb + AT_PH + aoff);
            }
            unsigned bh[2][4], bl[2][4];
            #pragma unroll
            for (int db2 = 0; db2 < 2; db2++) {
                int srow = ks2*16 + (lane & 7) + ((lane >> 3) & 1)*8;
                int dcol = wn*64 + db2*32 + (lane >> 4)*8;
                unsigned bo = (srow*136 + dcol)*2;
                ldsm4t(bh[db2], stVh + bo);
                ldsm4t(bl[db2], stVl + bo);
            }
            unsigned bh2[2][4], bl2[2][4];
            #pragma unroll
            for (int db2 = 0; db2 < 2; db2++) {
                int srow = ks2*16 + (lane & 7) + ((lane >> 3) & 1)*8;
                int dcol = wn*64 + db2*32 + 16 + (lane >> 4)*8;
                unsigned bo = (srow*136 + dcol)*2;
                ldsm4t(bh2[db2], stVh + bo);
                ldsm4t(bl2[db2], stVl + bo);
            }
            #pragma unroll
            for (int f = 0; f < 8; f++) {
                const int db2 = f >> 2, sub = f & 3;
                const unsigned* BH = (sub < 2) ? bh[db2] : bh2[db2];
                const unsigned* BL = (sub < 2) ? bl[db2] : bl2[db2];
                const int h = (sub & 1)*2;
                mma_f16(o[f], a_h, BH[h], BH[h+1]);
                mma_f16(o[f], a_h, BL[h], BL[h+1]);
            }
        }
    }

    // epilogue
    __syncthreads();
    {
        const float invA = 1.f / l_s[M0 + g];
        const float invB = 1.f / l_s[M0 + g + 8];
        float* Ob = out + ((size_t)b*SEQ + qbase)*HD;
        size_t rA = (size_t)(M0 + g);
        #pragma unroll
        for (int f = 0; f < 8; f++) {
            const int db2 = f >> 2, sub = f & 3;
            int col = wn*64 + db2*32 + (sub >> 1)*16 + (sub & 1)*8 + tg*2;
            *(float2*)(Ob + rA*HD + col)       = make_float2(o[f][0]*invA, o[f][1]*invA);
            *(float2*)(Ob + (rA + 8)*HD + col) = make_float2(o[f][2]*invB, o[f][3]*invB);
        }
    }
}

// ---------------------------------------------------------------------------
extern "C" void kernel_launch(void* const* d_in, const int* in_sizes, int n_in,
                              void* d_out, int out_size)
{
    const float* x  = (const float*)d_in[0];
    const float* Wk = (const float*)d_in[1];
    const float* Wq = (const float*)d_in[2];
    const float* Wv = (const float*)d_in[3];
    float* out = (float*)d_out;

    cudaFuncSetAttribute(qkv_proj_f16,
                         cudaFuncAttributeMaxDynamicSharedMemorySize, PJ_SMEM);
    cudaFuncSetAttribute(attn_f16_kernel,
                         cudaFuncAttributeMaxDynamicSharedMemorySize, AT_SMEM);

    dim3 g1(MROWS/128, 3);
    qkv_proj_f16<<<g1, 256, PJ_SMEM>>>(x, Wk, Wq, Wv);

    attn_f16_kernel<<<BATCH*(SEQ/64), 256, AT_SMEM>>>(out);
}